// round 4
// baseline (speedup 1.0000x reference)
#include <cuda_runtime.h>

// out[b,i,:] = c0[i]*H[b,base[i],:] + c1[i]*H[b,base[i]+1,:]
// Boundary extrapolation folded into (c0,c1,base) by coeff_kernel.
#define MAX_NFFT 8192
__device__ __align__(16) float2 g_coeff[MAX_NFFT];
__device__ __align__(16) int    g_base[MAX_NFFT];

__global__ void coeff_kernel(const float* __restrict__ pilot_pos,
                             const float* __restrict__ decay_param,
                             int NP, int Nfft) {
    extern __shared__ float s_loc[];  // extended knots: [0, loc..., Nfft-1]
    const int tid = threadIdx.x;
    for (int k = tid; k < NP; k += blockDim.x)
        s_loc[k + 1] = pilot_pos[k] - 1.0f;
    if (tid == 0) {
        s_loc[0]      = 0.0f;
        s_loc[NP + 1] = (float)(Nfft - 1);
    }
    __syncthreads();

    float dp = decay_param[0];
    float decay = (dp > 20.0f) ? dp : log1pf(expf(dp));

    int i = blockIdx.x * blockDim.x + tid;
    if (i >= Nfft) return;
    float fi = (float)i;

    // searchsorted(loc_ext, i, side='right') - 1, clipped
    int lo = 0, hi = NP + 2;
    while (lo < hi) {
        int mid = (lo + hi) >> 1;
        if (s_loc[mid] <= fi) lo = mid + 1; else hi = mid;
    }
    int left = lo - 1;
    if (left < 0)  left = 0;
    if (left > NP) left = NP;

    float x0 = s_loc[left], x1 = s_loc[left + 1];
    float wl = expf(-decay * fabsf(fi - x0));
    float wr = expf(-decay * fabsf(x1 - fi));
    float w  = wl + wr + 1e-12f;
    float al = wl / w, ar = wr / w;

    float c0, c1;
    int base;
    if (left == 0) {
        float l0 = s_loc[1], l1 = s_loc[2];
        float t = l0 / (l1 - l0);
        base = 0;
        c0 = al * (1.0f + t) + ar;
        c1 = -al * t;
    } else if (left == NP) {
        float lN1 = s_loc[NP], lN2 = s_loc[NP - 1];
        float u = ((float)(Nfft - 1) - lN1) / (lN1 - lN2);
        base = NP - 2;
        c0 = -ar * u;
        c1 = al + ar * (1.0f + u);
    } else {
        base = left - 1;
        c0 = al;
        c1 = ar;
    }
    g_coeff[i] = make_float2(c0, c1);
    g_base[i]  = base;
}

__device__ __forceinline__ void cp_async16(void* smem, const void* gmem) {
    unsigned s = (unsigned)__cvta_generic_to_shared(smem);
    asm volatile("cp.async.cg.shared.global [%0], [%1], 16;" :: "r"(s), "l"(gmem));
}
__device__ __forceinline__ void cp_commit() {
    asm volatile("cp.async.commit_group;");
}
template <int N>
__device__ __forceinline__ void cp_wait() {
    asm volatile("cp.async.wait_group %0;" :: "n"(N));
}

// Persistent single-wave kernel: each block processes rows_per_blk batch rows,
// double-buffering the H-row staging with cp.async so staging latency is
// hidden behind the previous row's compute+store.
__global__ void __launch_bounds__(256, 7)
interp_kernel(const float2* __restrict__ H,   // [B, NP]
              float* __restrict__ out,        // [B, Nfft, 2]
              int NP, int nf4,                 // nf4 = Nfft/2
              int rows_per_blk, int B) {
    extern __shared__ float2 sbuf[];           // 2 * NP float2
    const int tid = threadIdx.x;
    const int np4 = NP >> 1;                   // float4 chunks per row
    float2* sb0 = sbuf;
    float2* sb1 = sbuf + NP;

    const int row0 = blockIdx.x * rows_per_blk;
    const int rend = min(row0 + rows_per_blk, B);
    if (row0 >= B) return;

    // Prologue: stage first row into buffer 0.
    {
        const float4* src = (const float4*)(H + (size_t)row0 * NP);
        float4* dst = (float4*)sb0;
        for (int k = tid; k < np4; k += blockDim.x)
            cp_async16(dst + k, src + k);
        if ((NP & 1) && tid == 0) sb0[NP - 1] = H[(size_t)row0 * NP + NP - 1];
        cp_commit();
    }

    const float4* c4 = (const float4*)g_coeff;
    const int2*   b2 = (const int2*)g_base;

    for (int r = row0; r < rend; ++r) {
        float2* cur = ((r - row0) & 1) ? sb1 : sb0;
        float2* nxt = ((r - row0) & 1) ? sb0 : sb1;

        // Prefetch next row into the other buffer (its last readers finished
        // before the trailing __syncthreads of the previous iteration).
        bool has_next = (r + 1 < rend);
        if (has_next) {
            const float4* src = (const float4*)(H + (size_t)(r + 1) * NP);
            float4* dst = (float4*)nxt;
            for (int k = tid; k < np4; k += blockDim.x)
                cp_async16(dst + k, src + k);
            if ((NP & 1) && tid == 0) nxt[NP - 1] = H[(size_t)(r + 1) * NP + NP - 1];
            cp_commit();
            cp_wait<1>();   // current row's group complete; prefetch may fly
        } else {
            cp_wait<0>();
        }
        __syncthreads();

        float4* orow = (float4*)out + (size_t)r * nf4;
        #pragma unroll 4
        for (int f4 = tid; f4 < nf4; f4 += blockDim.x) {
            float4 c  = c4[f4];
            int2   bs = b2[f4];

            float2 y00 = cur[bs.x];
            float2 y01 = cur[bs.x + 1];
            float2 y10 = cur[bs.y];
            float2 y11 = cur[bs.y + 1];

            float4 v;
            v.x = c.x * y00.x + c.y * y01.x;
            v.y = c.x * y00.y + c.y * y01.y;
            v.z = c.z * y10.x + c.w * y11.x;
            v.w = c.z * y10.y + c.w * y11.y;

            __stcs(orow + f4, v);   // streaming store: never re-read
        }
        __syncthreads();  // all reads of 'cur' done before it is re-staged
    }
}

extern "C" void kernel_launch(void* const* d_in, const int* in_sizes, int n_in,
                              void* d_out, int out_size) {
    const float* LS_ri       = (const float*)d_in[0];  // [B, NP, 2]
    const float* pilot_pos   = (const float*)d_in[1];  // [NP]
    const float* decay_param = (const float*)d_in[2];  // [1]
    int NP   = in_sizes[1];
    int B    = in_sizes[0] / (NP * 2);
    int Nfft = out_size / (B * 2);

    // Kernel A: per-frequency coefficient table (tiny).
    {
        int threads = 256;
        int blocks  = (Nfft + threads - 1) / threads;
        size_t smem = (size_t)(NP + 2) * sizeof(float);
        coeff_kernel<<<blocks, threads, smem>>>(pilot_pos, decay_param, NP, Nfft);
    }

    // Kernel B: persistent single-wave, 4 rows per block, double-buffered.
    {
        int nf4 = Nfft / 2;
        int rows_per_blk = 4;
        int grid = (B + rows_per_blk - 1) / rows_per_blk;
        dim3 block(256);
        size_t smem = 2 * (size_t)NP * sizeof(float2);
        interp_kernel<<<grid, block, smem>>>((const float2*)LS_ri, (float*)d_out,
                                             NP, nf4, rows_per_blk, B);
    }
}